// round 7
// baseline (speedup 1.0000x reference)
#include <cuda_runtime.h>
#include <math.h>
#include <stdint.h>

#define NTOK 8192
#define DIM  1024
#define NEXP 8
#define BM   128
#define BN   128
#define BK   32
#define PADROWS (NTOK + NEXP*128)     // 9216 worst-case padded rows
#define PADTILES (PADROWS / 128)      // 72
#define SMEM_BYTES (2 * 2 * BK * 136 * 4)   // 2 buffers x (As+Bs) = 69632

// ---------------- device scratch (alloc-free rule) ----------------
__device__ int   g_eid[NTOK];
__device__ float g_w[NTOK];
__device__ int   g_counts[NEXP];
__device__ int   g_offs[NEXP];
__device__ int   g_fill[NEXP];
__device__ int   g_padcnt[NEXP];
__device__ int   g_pperm[PADROWS];
// k-major blocked: [tile][k][128 rows]
__device__ __align__(256) float g_xp[(size_t)PADTILES * DIM * 128];
__device__ __align__(256) float g_h [(size_t)PADTILES * DIM * 128];
// RNA-rounded weights (raw-copyable by cp.async)
__device__ __align__(256) float g_w1r[(size_t)NEXP * DIM * DIM];
__device__ __align__(256) float g_w2r[(size_t)NEXP * DIM * DIM];

__device__ __forceinline__ float to_tf32(float v) {
    float r; asm("cvt.rna.tf32.f32 %0, %1;" : "=f"(r) : "f"(v)); return r;
}
__device__ __forceinline__ uint32_t smem_u32(const void* p) {
    uint32_t a;
    asm("{ .reg .u64 t; cvta.to.shared.u64 t, %1; cvt.u32.u64 %0, t; }" : "=r"(a) : "l"(p));
    return a;
}
__device__ __forceinline__ void cp16(uint32_t s, const void* g) {
    asm volatile("cp.async.cg.shared.global [%0], [%1], 16;" :: "r"(s), "l"(g));
}

// ---------------- small kernels ----------------
__global__ void init_kernel() {
    int t = threadIdx.x;
    if (t < NEXP) g_counts[t] = 0;
}

__global__ void gate_kernel(const float* __restrict__ x,
                            const float* __restrict__ Wg,
                            const float* __restrict__ bg) {
    int warp = (blockIdx.x * blockDim.x + threadIdx.x) >> 5;
    int lane = threadIdx.x & 31;
    if (warp >= NTOK) return;
    const float* xr = x + (size_t)warp * DIM;
    float acc[NEXP];
#pragma unroll
    for (int e = 0; e < NEXP; e++) acc[e] = 0.f;
    for (int d = lane; d < DIM; d += 32) {
        float xv = xr[d];
        const float* wr = Wg + d * NEXP;
#pragma unroll
        for (int e = 0; e < NEXP; e++) acc[e] = fmaf(xv, wr[e], acc[e]);
    }
#pragma unroll
    for (int e = 0; e < NEXP; e++) {
#pragma unroll
        for (int o = 16; o > 0; o >>= 1)
            acc[e] += __shfl_xor_sync(0xffffffffu, acc[e], o);
    }
    if (lane == 0) {
        float l[NEXP];
        float best = -1e30f; int bi = 0;
#pragma unroll
        for (int e = 0; e < NEXP; e++) {
            l[e] = acc[e] + bg[e];
            if (l[e] > best) { best = l[e]; bi = e; }   // first-max, matches jnp.argmax
        }
        float s = 0.f;
#pragma unroll
        for (int e = 0; e < NEXP; e++) s += expf(l[e] - best);
        g_eid[warp] = bi;
        g_w[warp]   = 1.0f / s;
        atomicAdd(&g_counts[bi], 1);
    }
}

__global__ void scan_kernel() {
    if (threadIdx.x == 0) {
        int o = 0;
        for (int e = 0; e < NEXP; e++) {
            int pc = ((g_counts[e] + BM - 1) / BM) * BM;
            g_padcnt[e] = pc;
            g_offs[e] = o;
            g_fill[e] = o;
            o += pc;
        }
    }
}

__global__ void fillp_kernel() {
    int t = blockIdx.x * blockDim.x + threadIdx.x;
    if (t < PADROWS) g_pperm[t] = -1;
}

__global__ void scatter_kernel() {
    int t = blockIdx.x * blockDim.x + threadIdx.x;
    if (t < NTOK) {
        int pos = atomicAdd(&g_fill[g_eid[t]], 1);
        g_pperm[pos] = t;
    }
}

// RNA-round weights once (both GEMMs then cp.async raw bytes)
__global__ void roundW_kernel(const float* __restrict__ W, float* __restrict__ Wr) {
    size_t i = (size_t)blockIdx.x * blockDim.x + threadIdx.x;
    float4 v = ((const float4*)W)[i];
    v.x = to_tf32(v.x); v.y = to_tf32(v.y); v.z = to_tf32(v.z); v.w = to_tf32(v.w);
    ((float4*)Wr)[i] = v;
}

// One block per 128-row tile: transpose x rows (tf32-rounded) into g_xp[tile][k][m].
__global__ void copyxp_kernel(const float* __restrict__ x) {
    __shared__ float sm[32][133];
    const int tile = blockIdx.x;
    const int tid = threadIdx.x;
    const int base = tile * 128;

    for (int kc = 0; kc < DIM / 32; kc++) {
        __syncthreads();
#pragma unroll
        for (int i = 0; i < 4; i++) {
            int task = i * 256 + tid;
            int m = task >> 3;
            int c = task & 7;
            int tok = g_pperm[base + m];
            float4 v = (tok >= 0)
                ? *(const float4*)(x + (size_t)tok * DIM + kc * 32 + c * 4)
                : make_float4(0.f, 0.f, 0.f, 0.f);
            sm[c * 4 + 0][m] = to_tf32(v.x);
            sm[c * 4 + 1][m] = to_tf32(v.y);
            sm[c * 4 + 2][m] = to_tf32(v.z);
            sm[c * 4 + 3][m] = to_tf32(v.w);
        }
        __syncthreads();
        float* dst = g_xp + (size_t)tile * DIM * 128 + (size_t)kc * 32 * 128;
#pragma unroll
        for (int i = 0; i < 4; i++) {
            int task = i * 256 + tid;
            int k  = task >> 5;
            int ch = (task & 31) * 4;
            float4 o;
            o.x = sm[k][ch + 0]; o.y = sm[k][ch + 1];
            o.z = sm[k][ch + 2]; o.w = sm[k][ch + 3];
            *(float4*)(dst + (size_t)k * 128 + ch) = o;
        }
    }
}

// ---------------- tf32 mma.sync grouped GEMM, cp.async double-buffered ----------------
#define MMA_TF32(d, a, b)                                                        \
    asm volatile(                                                                \
        "mma.sync.aligned.m16n8k8.row.col.f32.tf32.tf32.f32 "                    \
        "{%0,%1,%2,%3}, {%4,%5,%6,%7}, {%8,%9}, {%0,%1,%2,%3};"                  \
        : "+f"((d)[0]), "+f"((d)[1]), "+f"((d)[2]), "+f"((d)[3])                 \
        : "r"((a)[0]), "r"((a)[1]), "r"((a)[2]), "r"((a)[3]),                    \
          "r"((b)[0]), "r"((b)[1]))

template <int STAGE>
__global__ void __launch_bounds__(256)
gemm_mma(const float* __restrict__ W, const float* __restrict__ Bias,
         float* __restrict__ out) {
    extern __shared__ float dynsm[];
    // layout: [buf][As 32x136][Bs 32x136]
    float (*As)[BK][136] = (float (*)[BK][136])dynsm;
    float (*Bs)[BK][136] = (float (*)[BK][136])(dynsm + 2 * BK * 136);

    const int e  = blockIdx.z;
    const int m0 = blockIdx.y * BM;
    if (m0 >= g_padcnt[e]) return;
    const int n0   = blockIdx.x * BN;
    const int off  = g_offs[e];
    const int tile = (off + m0) >> 7;

    const float* Abase = (STAGE == 1 ? g_xp : g_h) + (size_t)tile * DIM * 128;
    const float* Bbase = W + (size_t)e * DIM * DIM;

    const int tid  = threadIdx.x;
    const int lane = tid & 31;
    const int wid  = tid >> 5;
    const int wm   = (wid >> 2) * 64;
    const int wn   = (wid & 3) * 32;
    const int g    = lane >> 2;
    const int t4   = lane & 3;

    // per-thread staging coordinates: 4 x 16B chunks each for A and B
    const int skr = tid >> 3;           // 0..31 (row for chunks, +0 per i? no:)
    // We stage 1024 chunks per tile: task = i*256+tid, kr=task>>5, ch=(task&31)*4
    const uint32_t sA = smem_u32(&As[0][0][0]);
    const uint32_t sB = smem_u32(&Bs[0][0][0]);
    const uint32_t bufstride = BK * 136 * 4;   // bytes per buffer

    auto stage = [&](int it, int buf) {
        const int k0 = it * BK;
#pragma unroll
        for (int i = 0; i < 4; i++) {
            int task = i * 256 + tid;
            int kr = task >> 5;
            int ch = (task & 31) * 4;
            uint32_t so = (uint32_t)(kr * 136 + ch) * 4 + buf * bufstride;
            cp16(sA + so, Abase + (size_t)(k0 + kr) * 128 + ch);
            cp16(sB + so, Bbase + (size_t)(k0 + kr) * DIM + n0 + ch);
        }
        asm volatile("cp.async.commit_group;");
    };
    (void)skr;

    float acc[4][4][4];
#pragma unroll
    for (int mi = 0; mi < 4; mi++)
#pragma unroll
        for (int nj = 0; nj < 4; nj++)
#pragma unroll
            for (int r = 0; r < 4; r++) acc[mi][nj][r] = 0.f;

    const int NIT = DIM / BK;   // 32
    stage(0, 0);

    for (int it = 0; it < NIT; ++it) {
        const int cur = it & 1;
        if (it + 1 < NIT) {
            stage(it + 1, cur ^ 1);
            asm volatile("cp.async.wait_group 1;");
        } else {
            asm volatile("cp.async.wait_group 0;");
        }
        __syncthreads();

#pragma unroll
        for (int kk = 0; kk < 4; kk++) {
            const int kb = kk * 8;
            uint32_t a[4][4], b[4][2];
#pragma unroll
            for (int mi = 0; mi < 4; mi++) {
                int m = wm + mi * 16;
                a[mi][0] = __float_as_uint(As[cur][kb + t4    ][m + g    ]);
                a[mi][1] = __float_as_uint(As[cur][kb + t4    ][m + g + 8]);
                a[mi][2] = __float_as_uint(As[cur][kb + t4 + 4][m + g    ]);
                a[mi][3] = __float_as_uint(As[cur][kb + t4 + 4][m + g + 8]);
            }
#pragma unroll
            for (int nj = 0; nj < 4; nj++) {
                int n = wn + nj * 8;
                b[nj][0] = __float_as_uint(Bs[cur][kb + t4    ][n + g]);
                b[nj][1] = __float_as_uint(Bs[cur][kb + t4 + 4][n + g]);
            }
#pragma unroll
            for (int mi = 0; mi < 4; mi++)
#pragma unroll
                for (int nj = 0; nj < 4; nj++)
                    MMA_TF32(acc[mi][nj], a[mi], b[nj]);
        }
        __syncthreads();   // all warps done with 'cur' before it is re-staged
    }

    // ---- epilogue ----
    if (STAGE == 1) {
        float* Hbase = g_h + (size_t)tile * DIM * 128;
#pragma unroll
        for (int mi = 0; mi < 4; mi++) {
            int mA = wm + mi * 16 + g;
            int mB = mA + 8;
#pragma unroll
            for (int nj = 0; nj < 4; nj++) {
                int n = n0 + wn + nj * 8 + t4 * 2;
                float bi0 = Bias[e * DIM + n];
                float bi1 = Bias[e * DIM + n + 1];
                float v0 = acc[mi][nj][0] + bi0;
                float v1 = acc[mi][nj][1] + bi1;
                float v2 = acc[mi][nj][2] + bi0;
                float v3 = acc[mi][nj][3] + bi1;
                Hbase[(size_t)n * 128 + mA]       = to_tf32(0.5f * v0 * (1.0f + erff(v0 * 0.70710678118654752f)));
                Hbase[(size_t)(n + 1) * 128 + mA] = to_tf32(0.5f * v1 * (1.0f + erff(v1 * 0.70710678118654752f)));
                Hbase[(size_t)n * 128 + mB]       = to_tf32(0.5f * v2 * (1.0f + erff(v2 * 0.70710678118654752f)));
                Hbase[(size_t)(n + 1) * 128 + mB] = to_tf32(0.5f * v3 * (1.0f + erff(v3 * 0.70710678118654752f)));
            }
        }
    } else {
        const int prow = off + m0;
#pragma unroll
        for (int mi = 0; mi < 4; mi++) {
            int mA = wm + mi * 16 + g;
            int mB = mA + 8;
            int tokA = g_pperm[prow + mA];
            int tokB = g_pperm[prow + mB];
            float wA = (tokA >= 0) ? g_w[tokA] : 0.f;
            float wB = (tokB >= 0) ? g_w[tokB] : 0.f;
#pragma unroll
            for (int nj = 0; nj < 4; nj++) {
                int n = n0 + wn + nj * 8 + t4 * 2;
                float bi0 = Bias[e * DIM + n];
                float bi1 = Bias[e * DIM + n + 1];
                if (tokA >= 0) {
                    out[(size_t)tokA * DIM + n]     = wA * (acc[mi][nj][0] + bi0);
                    out[(size_t)tokA * DIM + n + 1] = wA * (acc[mi][nj][1] + bi1);
                }
                if (tokB >= 0) {
                    out[(size_t)tokB * DIM + n]     = wB * (acc[mi][nj][2] + bi0);
                    out[(size_t)tokB * DIM + n + 1] = wB * (acc[mi][nj][3] + bi1);
                }
            }
        }
    }
}

// ---------------------------------------------------------------------------
extern "C" void kernel_launch(void* const* d_in, const int* in_sizes, int n_in,
                              void* d_out, int out_size) {
    const float* x  = (const float*)d_in[0];
    const float* Wg = (const float*)d_in[1];
    const float* bg = (const float*)d_in[2];
    const float* W1 = (const float*)d_in[3];
    const float* b1 = (const float*)d_in[4];
    const float* W2 = (const float*)d_in[5];
    const float* b2 = (const float*)d_in[6];
    float* out = (float*)d_out;

    cudaFuncSetAttribute(gemm_mma<1>, cudaFuncAttributeMaxDynamicSharedMemorySize, SMEM_BYTES);
    cudaFuncSetAttribute(gemm_mma<2>, cudaFuncAttributeMaxDynamicSharedMemorySize, SMEM_BYTES);

    init_kernel<<<1, 32>>>();
    gate_kernel<<<(NTOK * 32 + 255) / 256, 256>>>(x, Wg, bg);
    scan_kernel<<<1, 32>>>();
    fillp_kernel<<<(PADROWS + 255) / 256, 256>>>();
    scatter_kernel<<<(NTOK + 255) / 256, 256>>>();
    copyxp_kernel<<<PADTILES, 256>>>(x);

    // round weights once (fits in L2 for the GEMMs)
    int wblocks = (int)(((size_t)NEXP * DIM * DIM / 4) / 256);
    roundW_kernel<<<wblocks, 256>>>(W1, g_w1r);
    roundW_kernel<<<wblocks, 256>>>(W2, g_w2r);

    dim3 grid(DIM / BN, PADTILES, NEXP);
    gemm_mma<1><<<grid, 256, SMEM_BYTES>>>(g_w1r, b1, nullptr);
    gemm_mma<2><<<grid, 256, SMEM_BYTES>>>(g_w2r, b2, out);
}

// round 8
// speedup vs baseline: 1.1460x; 1.1460x over previous
#include <cuda_runtime.h>
#include <math.h>
#include <stdint.h>

#define NTOK 8192
#define DIM  1024
#define NEXP 8
#define BM   128
#define BN   128
#define BK   32
#define PADROWS (NTOK + NEXP*128)     // 9216 worst-case padded rows
#define PADTILES (PADROWS / 128)      // 72
#define SMEM_BYTES (2 * 2 * BK * 136 * 4)   // 2 buffers x (As+Bs) = 69632

// ---------------- device scratch (alloc-free rule) ----------------
__device__ int   g_eid[NTOK];
__device__ float g_w[NTOK];
__device__ int   g_counts[NEXP];
__device__ int   g_offs[NEXP];
__device__ int   g_fill[NEXP];
__device__ int   g_padcnt[NEXP];
__device__ int   g_pperm[PADROWS];
// k-major blocked: [tile][k][128 rows]
__device__ __align__(256) float g_xp[(size_t)PADTILES * DIM * 128];
__device__ __align__(256) float g_h [(size_t)PADTILES * DIM * 128];
// RNA-rounded weights
__device__ __align__(256) float g_w1r[(size_t)NEXP * DIM * DIM];
__device__ __align__(256) float g_w2r[(size_t)NEXP * DIM * DIM];

__device__ __forceinline__ float to_tf32(float v) {
    float r; asm("cvt.rna.tf32.f32 %0, %1;" : "=f"(r) : "f"(v)); return r;
}

// ---------------- small kernels ----------------
__global__ void init_kernel() {
    int t = threadIdx.x;
    if (t < NEXP) g_counts[t] = 0;
}

__global__ void gate_kernel(const float* __restrict__ x,
                            const float* __restrict__ Wg,
                            const float* __restrict__ bg) {
    int warp = (blockIdx.x * blockDim.x + threadIdx.x) >> 5;
    int lane = threadIdx.x & 31;
    if (warp >= NTOK) return;
    const float* xr = x + (size_t)warp * DIM;
    float acc[NEXP];
#pragma unroll
    for (int e = 0; e < NEXP; e++) acc[e] = 0.f;
    for (int d = lane; d < DIM; d += 32) {
        float xv = xr[d];
        const float* wr = Wg + d * NEXP;
#pragma unroll
        for (int e = 0; e < NEXP; e++) acc[e] = fmaf(xv, wr[e], acc[e]);
    }
#pragma unroll
    for (int e = 0; e < NEXP; e++) {
#pragma unroll
        for (int o = 16; o > 0; o >>= 1)
            acc[e] += __shfl_xor_sync(0xffffffffu, acc[e], o);
    }
    if (lane == 0) {
        float l[NEXP];
        float best = -1e30f; int bi = 0;
#pragma unroll
        for (int e = 0; e < NEXP; e++) {
            l[e] = acc[e] + bg[e];
            if (l[e] > best) { best = l[e]; bi = e; }   // first-max, matches jnp.argmax
        }
        float s = 0.f;
#pragma unroll
        for (int e = 0; e < NEXP; e++) s += expf(l[e] - best);
        g_eid[warp] = bi;
        g_w[warp]   = 1.0f / s;
        atomicAdd(&g_counts[bi], 1);
    }
}

__global__ void scan_kernel() {
    if (threadIdx.x == 0) {
        int o = 0;
        for (int e = 0; e < NEXP; e++) {
            int pc = ((g_counts[e] + BM - 1) / BM) * BM;
            g_padcnt[e] = pc;
            g_offs[e] = o;
            g_fill[e] = o;
            o += pc;
        }
    }
}

__global__ void fillp_kernel() {
    int t = blockIdx.x * blockDim.x + threadIdx.x;
    if (t < PADROWS) g_pperm[t] = -1;
}

__global__ void scatter_kernel() {
    int t = blockIdx.x * blockDim.x + threadIdx.x;
    if (t < NTOK) {
        int pos = atomicAdd(&g_fill[g_eid[t]], 1);
        g_pperm[pos] = t;
    }
}

__global__ void roundW_kernel(const float* __restrict__ W, float* __restrict__ Wr) {
    size_t i = (size_t)blockIdx.x * blockDim.x + threadIdx.x;
    float4 v = ((const float4*)W)[i];
    v.x = to_tf32(v.x); v.y = to_tf32(v.y); v.z = to_tf32(v.z); v.w = to_tf32(v.w);
    ((float4*)Wr)[i] = v;
}

// One block per 128-row tile: transpose x rows (tf32-rounded) into g_xp[tile][k][m].
__global__ void copyxp_kernel(const float* __restrict__ x) {
    __shared__ float sm[32][133];
    const int tile = blockIdx.x;
    const int tid = threadIdx.x;
    const int base = tile * 128;

    for (int kc = 0; kc < DIM / 32; kc++) {
        __syncthreads();
#pragma unroll
        for (int i = 0; i < 4; i++) {
            int task = i * 256 + tid;
            int m = task >> 3;
            int c = task & 7;
            int tok = g_pperm[base + m];
            float4 v = (tok >= 0)
                ? *(const float4*)(x + (size_t)tok * DIM + kc * 32 + c * 4)
                : make_float4(0.f, 0.f, 0.f, 0.f);
            sm[c * 4 + 0][m] = to_tf32(v.x);
            sm[c * 4 + 1][m] = to_tf32(v.y);
            sm[c * 4 + 2][m] = to_tf32(v.z);
            sm[c * 4 + 3][m] = to_tf32(v.w);
        }
        __syncthreads();
        float* dst = g_xp + (size_t)tile * DIM * 128 + (size_t)kc * 32 * 128;
#pragma unroll
        for (int i = 0; i < 4; i++) {
            int task = i * 256 + tid;
            int k  = task >> 5;
            int ch = (task & 31) * 4;
            float4 o;
            o.x = sm[k][ch + 0]; o.y = sm[k][ch + 1];
            o.z = sm[k][ch + 2]; o.w = sm[k][ch + 3];
            *(float4*)(dst + (size_t)k * 128 + ch) = o;
        }
    }
}

// ---------------- tf32 mma.sync grouped GEMM, register-prefetch double buffer ----------------
#define MMA_TF32(d, a, b)                                                        \
    asm volatile(                                                                \
        "mma.sync.aligned.m16n8k8.row.col.f32.tf32.tf32.f32 "                    \
        "{%0,%1,%2,%3}, {%4,%5,%6,%7}, {%8,%9}, {%0,%1,%2,%3};"                  \
        : "+f"((d)[0]), "+f"((d)[1]), "+f"((d)[2]), "+f"((d)[3])                 \
        : "r"((a)[0]), "r"((a)[1]), "r"((a)[2]), "r"((a)[3]),                    \
          "r"((b)[0]), "r"((b)[1]))

template <int STAGE>
__global__ void __launch_bounds__(256)
gemm_mma(const float* __restrict__ W, const float* __restrict__ Bias,
         float* __restrict__ out) {
    extern __shared__ float dynsm[];
    float (*As)[BK][136] = (float (*)[BK][136])dynsm;                  // [2][32][136]
    float (*Bs)[BK][136] = (float (*)[BK][136])(dynsm + 2 * BK * 136); // [2][32][136]

    const int e  = blockIdx.z;
    const int m0 = blockIdx.y * BM;
    if (m0 >= g_padcnt[e]) return;
    const int n0   = blockIdx.x * BN;
    const int off  = g_offs[e];
    const int tile = (off + m0) >> 7;

    const float* Abase = (STAGE == 1 ? g_xp : g_h) + (size_t)tile * DIM * 128;
    const float* Bbase = W + (size_t)e * DIM * DIM;

    const int tid  = threadIdx.x;
    const int lane = tid & 31;
    const int wid  = tid >> 5;
    const int wm   = (wid >> 2) * 64;
    const int wn   = (wid & 3) * 32;
    const int g    = lane >> 2;
    const int t4   = lane & 3;

    // staging coordinates: each thread owns 4 (kr, ch) chunks, kr = wid + 8*i, ch = lane*4
    const int kr0 = wid;
    const int ch  = lane * 4;

    float4 pa[4], pb[4];   // prefetch registers

    float acc[4][4][4];
#pragma unroll
    for (int mi = 0; mi < 4; mi++)
#pragma unroll
        for (int nj = 0; nj < 4; nj++)
#pragma unroll
            for (int r = 0; r < 4; r++) acc[mi][nj][r] = 0.f;

    const int NIT = DIM / BK;   // 32

    // prologue: load + store k-iter 0 into buf 0
#pragma unroll
    for (int i = 0; i < 4; i++) {
        pa[i] = *(const float4*)(Abase + (size_t)(kr0 + 8 * i) * 128 + ch);
        pb[i] = *(const float4*)(Bbase + (size_t)(kr0 + 8 * i) * DIM + n0 + ch);
    }
#pragma unroll
    for (int i = 0; i < 4; i++) {
        *(float4*)&As[0][kr0 + 8 * i][ch] = pa[i];
        *(float4*)&Bs[0][kr0 + 8 * i][ch] = pb[i];
    }
    __syncthreads();

    for (int it = 0; it < NIT; ++it) {
        const int cur = it & 1;

        // prefetch next k-iter into registers (latency hidden by compute below)
        if (it + 1 < NIT) {
            const int k0 = (it + 1) * BK;
#pragma unroll
            for (int i = 0; i < 4; i++) {
                pa[i] = *(const float4*)(Abase + (size_t)(k0 + kr0 + 8 * i) * 128 + ch);
                pb[i] = *(const float4*)(Bbase + (size_t)(k0 + kr0 + 8 * i) * DIM + n0 + ch);
            }
        }

        // compute current buffer
#pragma unroll
        for (int kk = 0; kk < 4; kk++) {
            const int kb = kk * 8;
            uint32_t a[4][4], b[4][2];
#pragma unroll
            for (int mi = 0; mi < 4; mi++) {
                int m = wm + mi * 16;
                a[mi][0] = __float_as_uint(As[cur][kb + t4    ][m + g    ]);
                a[mi][1] = __float_as_uint(As[cur][kb + t4    ][m + g + 8]);
                a[mi][2] = __float_as_uint(As[cur][kb + t4 + 4][m + g    ]);
                a[mi][3] = __float_as_uint(As[cur][kb + t4 + 4][m + g + 8]);
            }
#pragma unroll
            for (int nj = 0; nj < 4; nj++) {
                int n = wn + nj * 8;
                b[nj][0] = __float_as_uint(Bs[cur][kb + t4    ][n + g]);
                b[nj][1] = __float_as_uint(Bs[cur][kb + t4 + 4][n + g]);
            }
#pragma unroll
            for (int mi = 0; mi < 4; mi++)
#pragma unroll
                for (int nj = 0; nj < 4; nj++)
                    MMA_TF32(acc[mi][nj], a[mi], b[nj]);
        }

        // store prefetched tile into the other buffer (safe: last read of cur^1
        // finished before the sync that ended iteration it-1)
        if (it + 1 < NIT) {
            const int nxt = cur ^ 1;
#pragma unroll
            for (int i = 0; i < 4; i++) {
                *(float4*)&As[nxt][kr0 + 8 * i][ch] = pa[i];
                *(float4*)&Bs[nxt][kr0 + 8 * i][ch] = pb[i];
            }
        }
        __syncthreads();
    }

    // ---- epilogue ----
    if (STAGE == 1) {
        float* Hbase = g_h + (size_t)tile * DIM * 128;
#pragma unroll
        for (int mi = 0; mi < 4; mi++) {
            int mA = wm + mi * 16 + g;
            int mB = mA + 8;
#pragma unroll
            for (int nj = 0; nj < 4; nj++) {
                int n = n0 + wn + nj * 8 + t4 * 2;
                float bi0 = Bias[e * DIM + n];
                float bi1 = Bias[e * DIM + n + 1];
                float v0 = acc[mi][nj][0] + bi0;
                float v1 = acc[mi][nj][1] + bi1;
                float v2 = acc[mi][nj][2] + bi0;
                float v3 = acc[mi][nj][3] + bi1;
                Hbase[(size_t)n * 128 + mA]       = to_tf32(0.5f * v0 * (1.0f + erff(v0 * 0.70710678118654752f)));
                Hbase[(size_t)(n + 1) * 128 + mA] = to_tf32(0.5f * v1 * (1.0f + erff(v1 * 0.70710678118654752f)));
                Hbase[(size_t)n * 128 + mB]       = to_tf32(0.5f * v2 * (1.0f + erff(v2 * 0.70710678118654752f)));
                Hbase[(size_t)(n + 1) * 128 + mB] = to_tf32(0.5f * v3 * (1.0f + erff(v3 * 0.70710678118654752f)));
            }
        }
    } else {
        const int prow = off + m0;
#pragma unroll
        for (int mi = 0; mi < 4; mi++) {
            int mA = wm + mi * 16 + g;
            int mB = mA + 8;
            int tokA = g_pperm[prow + mA];
            int tokB = g_pperm[prow + mB];
            float wA = (tokA >= 0) ? g_w[tokA] : 0.f;
            float wB = (tokB >= 0) ? g_w[tokB] : 0.f;
#pragma unroll
            for (int nj = 0; nj < 4; nj++) {
                int n = n0 + wn + nj * 8 + t4 * 2;
                float bi0 = Bias[e * DIM + n];
                float bi1 = Bias[e * DIM + n + 1];
                if (tokA >= 0) {
                    out[(size_t)tokA * DIM + n]     = wA * (acc[mi][nj][0] + bi0);
                    out[(size_t)tokA * DIM + n + 1] = wA * (acc[mi][nj][1] + bi1);
                }
                if (tokB >= 0) {
                    out[(size_t)tokB * DIM + n]     = wB * (acc[mi][nj][2] + bi0);
                    out[(size_t)tokB * DIM + n + 1] = wB * (acc[mi][nj][3] + bi1);
                }
            }
        }
    }
}

// ---------------------------------------------------------------------------
extern "C" void kernel_launch(void* const* d_in, const int* in_sizes, int n_in,
                              void* d_out, int out_size) {
    const float* x  = (const float*)d_in[0];
    const float* Wg = (const float*)d_in[1];
    const float* bg = (const float*)d_in[2];
    const float* W1 = (const float*)d_in[3];
    const float* b1 = (const float*)d_in[4];
    const float* W2 = (const float*)d_in[5];
    const float* b2 = (const float*)d_in[6];
    float* out = (float*)d_out;

    cudaFuncSetAttribute(gemm_mma<1>, cudaFuncAttributeMaxDynamicSharedMemorySize, SMEM_BYTES);
    cudaFuncSetAttribute(gemm_mma<2>, cudaFuncAttributeMaxDynamicSharedMemorySize, SMEM_BYTES);

    init_kernel<<<1, 32>>>();
    gate_kernel<<<(NTOK * 32 + 255) / 256, 256>>>(x, Wg, bg);
    scan_kernel<<<1, 32>>>();
    fillp_kernel<<<(PADROWS + 255) / 256, 256>>>();
    scatter_kernel<<<(NTOK + 255) / 256, 256>>>();
    copyxp_kernel<<<PADTILES, 256>>>(x);

    int wblocks = (int)(((size_t)NEXP * DIM * DIM / 4) / 256);
    roundW_kernel<<<wblocks, 256>>>(W1, g_w1r);
    roundW_kernel<<<wblocks, 256>>>(W2, g_w2r);

    dim3 grid(DIM / BN, PADTILES, NEXP);
    gemm_mma<1><<<grid, 256, SMEM_BYTES>>>(g_w1r, b1, nullptr);
    gemm_mma<2><<<grid, 256, SMEM_BYTES>>>(g_w2r, b2, out);
}

// round 11
// speedup vs baseline: 8.3939x; 7.3247x over previous
#include <cuda_runtime.h>
#include <math.h>
#include <stdint.h>

#define NTOK 8192
#define DIM  1024
#define NEXP 8
#define BM   128
#define BN   128
#define BK   32
#define PADROWS (NTOK + NEXP*128)     // 9216 worst-case padded rows
#define PADTILES (PADROWS / 128)      // 72

// ---------------- device scratch (alloc-free rule) ----------------
// NOTE: these symbols must ONLY be referenced from device code. Passing them as
// host-side kernel arguments passes the HOST shadow address (ATS makes it "work"
// by reading host memory) — root cause of the R7-R10 anomalies.
__device__ int   g_eid[NTOK];
__device__ float g_w[NTOK];
__device__ int   g_counts[NEXP];
__device__ int   g_offs[NEXP];
__device__ int   g_fill[NEXP];
__device__ int   g_padcnt[NEXP];
__device__ int   g_pperm[PADROWS];
// k-major blocked: [tile][k][128 rows]
__device__ __align__(256) float g_xp[(size_t)PADTILES * DIM * 128];
__device__ __align__(256) float g_h [(size_t)PADTILES * DIM * 128];
// RNA-rounded weights (device-resident)
__device__ __align__(256) float g_w1r[(size_t)NEXP * DIM * DIM];
__device__ __align__(256) float g_w2r[(size_t)NEXP * DIM * DIM];

__device__ __forceinline__ float to_tf32(float v) {
    float r; asm("cvt.rna.tf32.f32 %0, %1;" : "=f"(r) : "f"(v)); return r;
}

// ---------------- fused prep: init counts + fill perm + round both W ----------------
// grid = 16384 blocks x 256 threads: one float4 of W per thread (2M per matrix).
__global__ void prep_kernel(const float* __restrict__ W1, const float* __restrict__ W2) {
    const int b = blockIdx.x, t = threadIdx.x;
    if (b == 0 && t < NEXP) g_counts[t] = 0;
    int pidx = b * 256 + t;
    if (pidx < PADROWS) g_pperm[pidx] = -1;

    size_t i = (size_t)b * 256 + t;                      // 0 .. 4M-1
    const size_t HALF = (size_t)NEXP * DIM * DIM / 4;    // 2M float4 per matrix
    if (i < HALF) {
        float4 v = ((const float4*)W1)[i];
        v.x = to_tf32(v.x); v.y = to_tf32(v.y); v.z = to_tf32(v.z); v.w = to_tf32(v.w);
        ((float4*)g_w1r)[i] = v;
    } else {
        size_t j = i - HALF;
        float4 v = ((const float4*)W2)[j];
        v.x = to_tf32(v.x); v.y = to_tf32(v.y); v.z = to_tf32(v.z); v.w = to_tf32(v.w);
        ((float4*)g_w2r)[j] = v;
    }
}

// ---------------- gating ----------------
__global__ void gate_kernel(const float* __restrict__ x,
                            const float* __restrict__ Wg,
                            const float* __restrict__ bg) {
    int warp = (blockIdx.x * blockDim.x + threadIdx.x) >> 5;
    int lane = threadIdx.x & 31;
    if (warp >= NTOK) return;
    const float* xr = x + (size_t)warp * DIM;
    float acc[NEXP];
#pragma unroll
    for (int e = 0; e < NEXP; e++) acc[e] = 0.f;
    for (int d = lane; d < DIM; d += 32) {
        float xv = xr[d];
        const float* wr = Wg + d * NEXP;
#pragma unroll
        for (int e = 0; e < NEXP; e++) acc[e] = fmaf(xv, wr[e], acc[e]);
    }
#pragma unroll
    for (int e = 0; e < NEXP; e++) {
#pragma unroll
        for (int o = 16; o > 0; o >>= 1)
            acc[e] += __shfl_xor_sync(0xffffffffu, acc[e], o);
    }
    if (lane == 0) {
        float l[NEXP];
        float best = -1e30f; int bi = 0;
#pragma unroll
        for (int e = 0; e < NEXP; e++) {
            l[e] = acc[e] + bg[e];
            if (l[e] > best) { best = l[e]; bi = e; }   // first-max, matches jnp.argmax
        }
        float s = 0.f;
#pragma unroll
        for (int e = 0; e < NEXP; e++) s += expf(l[e] - best);
        g_eid[warp] = bi;
        g_w[warp]   = 1.0f / s;
        atomicAdd(&g_counts[bi], 1);
    }
}

__global__ void scan_kernel() {
    if (threadIdx.x == 0) {
        int o = 0;
        for (int e = 0; e < NEXP; e++) {
            int pc = ((g_counts[e] + BM - 1) / BM) * BM;
            g_padcnt[e] = pc;
            g_offs[e] = o;
            g_fill[e] = o;
            o += pc;
        }
    }
}

__global__ void scatter_kernel() {
    int t = blockIdx.x * blockDim.x + threadIdx.x;
    if (t < NTOK) {
        int pos = atomicAdd(&g_fill[g_eid[t]], 1);
        g_pperm[pos] = t;
    }
}

// One block per 128-row tile: transpose x rows (tf32-rounded) into g_xp[tile][k][m].
__global__ void copyxp_kernel(const float* __restrict__ x) {
    __shared__ float sm[32][133];
    const int tile = blockIdx.x;
    const int tid = threadIdx.x;
    const int base = tile * 128;

    for (int kc = 0; kc < DIM / 32; kc++) {
        __syncthreads();
#pragma unroll
        for (int i = 0; i < 4; i++) {
            int task = i * 256 + tid;
            int m = task >> 3;
            int c = task & 7;
            int tok = g_pperm[base + m];
            float4 v = (tok >= 0)
                ? *(const float4*)(x + (size_t)tok * DIM + kc * 32 + c * 4)
                : make_float4(0.f, 0.f, 0.f, 0.f);
            sm[c * 4 + 0][m] = to_tf32(v.x);
            sm[c * 4 + 1][m] = to_tf32(v.y);
            sm[c * 4 + 2][m] = to_tf32(v.z);
            sm[c * 4 + 3][m] = to_tf32(v.w);
        }
        __syncthreads();
        float* dst = g_xp + (size_t)tile * DIM * 128 + (size_t)kc * 32 * 128;
#pragma unroll
        for (int i = 0; i < 4; i++) {
            int task = i * 256 + tid;
            int k  = task >> 5;
            int ch = (task & 31) * 4;
            float4 o;
            o.x = sm[k][ch + 0]; o.y = sm[k][ch + 1];
            o.z = sm[k][ch + 2]; o.w = sm[k][ch + 3];
            *(float4*)(dst + (size_t)k * 128 + ch) = o;
        }
    }
}

// ---------------- tf32 mma.sync grouped GEMM (proven R5 structure) ----------------
// All device-scratch operands (A tiles, W tiles) are resolved INSIDE device code.
#define MMA_TF32(d, a, b)                                                        \
    asm volatile(                                                                \
        "mma.sync.aligned.m16n8k8.row.col.f32.tf32.tf32.f32 "                    \
        "{%0,%1,%2,%3}, {%4,%5,%6,%7}, {%8,%9}, {%0,%1,%2,%3};"                  \
        : "+f"((d)[0]), "+f"((d)[1]), "+f"((d)[2]), "+f"((d)[3])                 \
        : "r"((a)[0]), "r"((a)[1]), "r"((a)[2]), "r"((a)[3]),                    \
          "r"((b)[0]), "r"((b)[1]))

template <int STAGE>
__global__ void __launch_bounds__(256, 2)
gemm_mma(const float* __restrict__ Bias, float* __restrict__ out) {
    __shared__ float As[BK][136];
    __shared__ float Bs[BK][136];

    const int e  = blockIdx.z;
    const int m0 = blockIdx.y * BM;
    if (m0 >= g_padcnt[e]) return;
    const int n0   = blockIdx.x * BN;
    const int off  = g_offs[e];
    const int tile = (off + m0) >> 7;

    const float* Abase = (STAGE == 1 ? g_xp : g_h) + (size_t)tile * DIM * 128;
    const float* Bbase = (STAGE == 1 ? g_w1r : g_w2r) + (size_t)e * DIM * DIM;

    const int tid  = threadIdx.x;
    const int lane = tid & 31;
    const int wid  = tid >> 5;
    const int wm   = (wid >> 2) * 64;
    const int wn   = (wid & 3) * 32;
    const int g    = lane >> 2;
    const int t4   = lane & 3;

    float acc[4][4][4];
#pragma unroll
    for (int mi = 0; mi < 4; mi++)
#pragma unroll
        for (int nj = 0; nj < 4; nj++)
#pragma unroll
            for (int r = 0; r < 4; r++) acc[mi][nj][r] = 0.f;

    for (int k0 = 0; k0 < DIM; k0 += BK) {
        // ---- stage tiles (A and B both pre-rounded; raw copies) ----
#pragma unroll
        for (int i = 0; i < 4; i++) {
            int task = i * 256 + tid;
            int kr = task >> 5;
            int ch = (task & 31) * 4;
            float4 va = *(const float4*)(Abase + (size_t)(k0 + kr) * 128 + ch);
            *(float4*)&As[kr][ch] = va;
            float4 vb = *(const float4*)(Bbase + (size_t)(k0 + kr) * DIM + n0 + ch);
            *(float4*)&Bs[kr][ch] = vb;
        }
        __syncthreads();

        // ---- compute ----
#pragma unroll
        for (int kk = 0; kk < 4; kk++) {
            const int kb = kk * 8;
            uint32_t a[4][4], b[4][2];
#pragma unroll
            for (int mi = 0; mi < 4; mi++) {
                int m = wm + mi * 16;
                a[mi][0] = __float_as_uint(As[kb + t4    ][m + g    ]);
                a[mi][1] = __float_as_uint(As[kb + t4    ][m + g + 8]);
                a[mi][2] = __float_as_uint(As[kb + t4 + 4][m + g    ]);
                a[mi][3] = __float_as_uint(As[kb + t4 + 4][m + g + 8]);
            }
#pragma unroll
            for (int nj = 0; nj < 4; nj++) {
                int n = wn + nj * 8;
                b[nj][0] = __float_as_uint(Bs[kb + t4    ][n + g]);
                b[nj][1] = __float_as_uint(Bs[kb + t4 + 4][n + g]);
            }
#pragma unroll
            for (int mi = 0; mi < 4; mi++)
#pragma unroll
                for (int nj = 0; nj < 4; nj++)
                    MMA_TF32(acc[mi][nj], a[mi], b[nj]);
        }
        __syncthreads();
    }

    // ---- epilogue ----
    if (STAGE == 1) {
        float* Hbase = g_h + (size_t)tile * DIM * 128;
#pragma unroll
        for (int mi = 0; mi < 4; mi++) {
            int mA = wm + mi * 16 + g;
            int mB = mA + 8;
#pragma unroll
            for (int nj = 0; nj < 4; nj++) {
                int n = n0 + wn + nj * 8 + t4 * 2;
                float bi0 = Bias[e * DIM + n];
                float bi1 = Bias[e * DIM + n + 1];
                float v0 = acc[mi][nj][0] + bi0;
                float v1 = acc[mi][nj][1] + bi1;
                float v2 = acc[mi][nj][2] + bi0;
                float v3 = acc[mi][nj][3] + bi1;
                Hbase[(size_t)n * 128 + mA]       = to_tf32(0.5f * v0 * (1.0f + erff(v0 * 0.70710678118654752f)));
                Hbase[(size_t)(n + 1) * 128 + mA] = to_tf32(0.5f * v1 * (1.0f + erff(v1 * 0.70710678118654752f)));
                Hbase[(size_t)n * 128 + mB]       = to_tf32(0.5f * v2 * (1.0f + erff(v2 * 0.70710678118654752f)));
                Hbase[(size_t)(n + 1) * 128 + mB] = to_tf32(0.5f * v3 * (1.0f + erff(v3 * 0.70710678118654752f)));
            }
        }
    } else {
        const int prow = off + m0;
#pragma unroll
        for (int mi = 0; mi < 4; mi++) {
            int mA = wm + mi * 16 + g;
            int mB = mA + 8;
            int tokA = g_pperm[prow + mA];
            int tokB = g_pperm[prow + mB];
            float wA = (tokA >= 0) ? g_w[tokA] : 0.f;
            float wB = (tokB >= 0) ? g_w[tokB] : 0.f;
#pragma unroll
            for (int nj = 0; nj < 4; nj++) {
                int n = n0 + wn + nj * 8 + t4 * 2;
                float bi0 = Bias[e * DIM + n];
                float bi1 = Bias[e * DIM + n + 1];
                if (tokA >= 0) {
                    out[(size_t)tokA * DIM + n]     = wA * (acc[mi][nj][0] + bi0);
                    out[(size_t)tokA * DIM + n + 1] = wA * (acc[mi][nj][1] + bi1);
                }
                if (tokB >= 0) {
                    out[(size_t)tokB * DIM + n]     = wB * (acc[mi][nj][2] + bi0);
                    out[(size_t)tokB * DIM + n + 1] = wB * (acc[mi][nj][3] + bi1);
                }
            }
        }
    }
}

// ---------------------------------------------------------------------------
extern "C" void kernel_launch(void* const* d_in, const int* in_sizes, int n_in,
                              void* d_out, int out_size) {
    const float* x  = (const float*)d_in[0];
    const float* Wg = (const float*)d_in[1];
    const float* bg = (const float*)d_in[2];
    const float* W1 = (const float*)d_in[3];
    const float* b1 = (const float*)d_in[4];
    const float* W2 = (const float*)d_in[5];
    const float* b2 = (const float*)d_in[6];
    float* out = (float*)d_out;

    // launch order chosen so ncu (-s 5 -c 1) profiles gemm_mma<1>
    prep_kernel<<<16384, 256>>>(W1, W2);                       // 1
    gate_kernel<<<(NTOK * 32 + 255) / 256, 256>>>(x, Wg, bg);  // 2
    scan_kernel<<<1, 32>>>();                                  // 3
    scatter_kernel<<<(NTOK + 255) / 256, 256>>>();             // 4
    copyxp_kernel<<<PADTILES, 256>>>(x);                       // 5

    dim3 grid(DIM / BN, PADTILES, NEXP);
    gemm_mma<1><<<grid, 256>>>(b1, nullptr);                   // 6 <- profiled
    gemm_mma<2><<<grid, 256>>>(b2, out);                       // 7
}

// round 12
// speedup vs baseline: 8.7965x; 1.0480x over previous
#include <cuda_runtime.h>
#include <math.h>
#include <stdint.h>

#define NTOK 8192
#define DIM  1024
#define NEXP 8
#define BM   128
#define BN   128
#define BK   16
#define PADROWS (NTOK + NEXP*128)     // 9216 worst-case padded rows
#define PADTILES (PADROWS / 128)      // 72

// ---------------- device scratch (alloc-free rule) ----------------
// NOTE: reference these ONLY from device code (host-side use passes the host
// shadow address via ATS — root cause of the R7-R10 anomalies).
__device__ int   g_eid[NTOK];
__device__ float g_w[NTOK];
__device__ int   g_counts[NEXP];
__device__ int   g_offs[NEXP];
__device__ int   g_fill[NEXP];
__device__ int   g_padcnt[NEXP];
__device__ int   g_pperm[PADROWS];
// k-major blocked: [tile][k][128 rows]
__device__ __align__(256) float g_xp[(size_t)PADTILES * DIM * 128];
__device__ __align__(256) float g_h [(size_t)PADTILES * DIM * 128];
// RNA-rounded weights (device-resident)
__device__ __align__(256) float g_w1r[(size_t)NEXP * DIM * DIM];
__device__ __align__(256) float g_w2r[(size_t)NEXP * DIM * DIM];

__device__ __forceinline__ float to_tf32(float v) {
    float r; asm("cvt.rna.tf32.f32 %0, %1;" : "=f"(r) : "f"(v)); return r;
}

// ---------------- fused prep: init counts + fill perm + round both W ----------------
__global__ void prep_kernel(const float* __restrict__ W1, const float* __restrict__ W2) {
    const int b = blockIdx.x, t = threadIdx.x;
    if (b == 0 && t < NEXP) g_counts[t] = 0;
    int pidx = b * 256 + t;
    if (pidx < PADROWS) g_pperm[pidx] = -1;

    size_t i = (size_t)b * 256 + t;                      // 0 .. 4M-1
    const size_t HALF = (size_t)NEXP * DIM * DIM / 4;    // 2M float4 per matrix
    if (i < HALF) {
        float4 v = ((const float4*)W1)[i];
        v.x = to_tf32(v.x); v.y = to_tf32(v.y); v.z = to_tf32(v.z); v.w = to_tf32(v.w);
        ((float4*)g_w1r)[i] = v;
    } else {
        size_t j = i - HALF;
        float4 v = ((const float4*)W2)[j];
        v.x = to_tf32(v.x); v.y = to_tf32(v.y); v.z = to_tf32(v.z); v.w = to_tf32(v.w);
        ((float4*)g_w2r)[j] = v;
    }
}

// ---------------- gating ----------------
__global__ void gate_kernel(const float* __restrict__ x,
                            const float* __restrict__ Wg,
                            const float* __restrict__ bg) {
    int warp = (blockIdx.x * blockDim.x + threadIdx.x) >> 5;
    int lane = threadIdx.x & 31;
    if (warp >= NTOK) return;
    const float* xr = x + (size_t)warp * DIM;
    float acc[NEXP];
#pragma unroll
    for (int e = 0; e < NEXP; e++) acc[e] = 0.f;
    for (int d = lane; d < DIM; d += 32) {
        float xv = xr[d];
        const float* wr = Wg + d * NEXP;
#pragma unroll
        for (int e = 0; e < NEXP; e++) acc[e] = fmaf(xv, wr[e], acc[e]);
    }
#pragma unroll
    for (int e = 0; e < NEXP; e++) {
#pragma unroll
        for (int o = 16; o > 0; o >>= 1)
            acc[e] += __shfl_xor_sync(0xffffffffu, acc[e], o);
    }
    if (lane == 0) {
        float l[NEXP];
        float best = -1e30f; int bi = 0;
#pragma unroll
        for (int e = 0; e < NEXP; e++) {
            l[e] = acc[e] + bg[e];
            if (l[e] > best) { best = l[e]; bi = e; }   // first-max, matches jnp.argmax
        }
        float s = 0.f;
#pragma unroll
        for (int e = 0; e < NEXP; e++) s += expf(l[e] - best);
        g_eid[warp] = bi;
        g_w[warp]   = 1.0f / s;
        atomicAdd(&g_counts[bi], 1);
    }
}

__global__ void scan_kernel() {
    if (threadIdx.x == 0) {
        int o = 0;
        for (int e = 0; e < NEXP; e++) {
            int pc = ((g_counts[e] + BM - 1) / BM) * BM;
            g_padcnt[e] = pc;
            g_offs[e] = o;
            g_fill[e] = o;
            o += pc;
        }
    }
}

__global__ void scatter_kernel() {
    int t = blockIdx.x * blockDim.x + threadIdx.x;
    if (t < NTOK) {
        int pos = atomicAdd(&g_fill[g_eid[t]], 1);
        g_pperm[pos] = t;
    }
}

// One block per 128-row tile: transpose x rows (tf32-rounded) into g_xp[tile][k][m].
__global__ void copyxp_kernel(const float* __restrict__ x) {
    __shared__ float sm[32][133];
    const int tile = blockIdx.x;
    const int tid = threadIdx.x;
    const int base = tile * 128;

    for (int kc = 0; kc < DIM / 32; kc++) {
        __syncthreads();
#pragma unroll
        for (int i = 0; i < 4; i++) {
            int task = i * 256 + tid;
            int m = task >> 3;
            int c = task & 7;
            int tok = g_pperm[base + m];
            float4 v = (tok >= 0)
                ? *(const float4*)(x + (size_t)tok * DIM + kc * 32 + c * 4)
                : make_float4(0.f, 0.f, 0.f, 0.f);
            sm[c * 4 + 0][m] = to_tf32(v.x);
            sm[c * 4 + 1][m] = to_tf32(v.y);
            sm[c * 4 + 2][m] = to_tf32(v.z);
            sm[c * 4 + 3][m] = to_tf32(v.w);
        }
        __syncthreads();
        float* dst = g_xp + (size_t)tile * DIM * 128 + (size_t)kc * 32 * 128;
#pragma unroll
        for (int i = 0; i < 4; i++) {
            int task = i * 256 + tid;
            int k  = task >> 5;
            int ch = (task & 31) * 4;
            float4 o;
            o.x = sm[k][ch + 0]; o.y = sm[k][ch + 1];
            o.z = sm[k][ch + 2]; o.w = sm[k][ch + 3];
            *(float4*)(dst + (size_t)k * 128 + ch) = o;
        }
    }
}

// ---------------- tf32 mma.sync grouped GEMM ----------------
// BK=16 register-prefetch double buffer at occupancy 2 (34816 B static smem).
#define MMA_TF32(d, a, b)                                                        \
    asm volatile(                                                                \
        "mma.sync.aligned.m16n8k8.row.col.f32.tf32.tf32.f32 "                    \
        "{%0,%1,%2,%3}, {%4,%5,%6,%7}, {%8,%9}, {%0,%1,%2,%3};"                  \
        : "+f"((d)[0]), "+f"((d)[1]), "+f"((d)[2]), "+f"((d)[3])                 \
        : "r"((a)[0]), "r"((a)[1]), "r"((a)[2]), "r"((a)[3]),                    \
          "r"((b)[0]), "r"((b)[1]))

template <int STAGE>
__global__ void __launch_bounds__(256, 2)
gemm_mma(const float* __restrict__ Bias, float* __restrict__ out) {
    __shared__ float As[2][BK][136];
    __shared__ float Bs[2][BK][136];

    const int e  = blockIdx.z;
    const int m0 = blockIdx.y * BM;
    if (m0 >= g_padcnt[e]) return;
    const int n0   = blockIdx.x * BN;
    const int off  = g_offs[e];
    const int tile = (off + m0) >> 7;

    const float* Abase = (STAGE == 1 ? g_xp : g_h) + (size_t)tile * DIM * 128;
    const float* Bbase = (STAGE == 1 ? g_w1r : g_w2r) + (size_t)e * DIM * DIM;

    const int tid  = threadIdx.x;
    const int lane = tid & 31;
    const int wid  = tid >> 5;
    const int wm   = (wid >> 2) * 64;
    const int wn   = (wid & 3) * 32;
    const int g    = lane >> 2;
    const int t4   = lane & 3;

    // staging: 512 float4 per operand tile, 2 per thread (kr = tid>>5 + 8i, ch = (tid&31)*4)
    const int krA = tid >> 5;
    const int chA = (tid & 31) * 4;

    float4 pa[2], pb[2];

    float acc[4][4][4];
#pragma unroll
    for (int mi = 0; mi < 4; mi++)
#pragma unroll
        for (int nj = 0; nj < 4; nj++)
#pragma unroll
            for (int r = 0; r < 4; r++) acc[mi][nj][r] = 0.f;

    const int NIT = DIM / BK;   // 64

    // prologue: k-slab 0 -> buf 0
#pragma unroll
    for (int i = 0; i < 2; i++) {
        int kr = krA + 8 * i;
        pa[i] = *(const float4*)(Abase + (size_t)kr * 128 + chA);
        pb[i] = *(const float4*)(Bbase + (size_t)kr * DIM + n0 + chA);
    }
#pragma unroll
    for (int i = 0; i < 2; i++) {
        int kr = krA + 8 * i;
        *(float4*)&As[0][kr][chA] = pa[i];
        *(float4*)&Bs[0][kr][chA] = pb[i];
    }
    __syncthreads();

    for (int it = 0; it < NIT; ++it) {
        const int cur = it & 1;

        // prefetch next k-slab into registers (hidden under the MMAs below)
        if (it + 1 < NIT) {
            const int k0 = (it + 1) * BK;
#pragma unroll
            for (int i = 0; i < 2; i++) {
                int kr = k0 + krA + 8 * i;
                pa[i] = *(const float4*)(Abase + (size_t)kr * 128 + chA);
                pb[i] = *(const float4*)(Bbase + (size_t)kr * DIM + n0 + chA);
            }
        }

        // compute current buffer (2 x K=8)
#pragma unroll
        for (int kk = 0; kk < 2; kk++) {
            const int kb = kk * 8;
            uint32_t a[4][4], b[4][2];
#pragma unroll
            for (int mi = 0; mi < 4; mi++) {
                int m = wm + mi * 16;
                a[mi][0] = __float_as_uint(As[cur][kb + t4    ][m + g    ]);
                a[mi][1] = __float_as_uint(As[cur][kb + t4    ][m + g + 8]);
                a[mi][2] = __float_as_uint(As[cur][kb + t4 + 4][m + g    ]);
                a[mi][3] = __float_as_uint(As[cur][kb + t4 + 4][m + g + 8]);
            }
#pragma unroll
            for (int nj = 0; nj < 4; nj++) {
                int n = wn + nj * 8;
                b[nj][0] = __float_as_uint(Bs[cur][kb + t4    ][n + g]);
                b[nj][1] = __float_as_uint(Bs[cur][kb + t4 + 4][n + g]);
            }
#pragma unroll
            for (int mi = 0; mi < 4; mi++)
#pragma unroll
                for (int nj = 0; nj < 4; nj++)
                    MMA_TF32(acc[mi][nj], a[mi], b[nj]);
        }

        // store prefetched slab into the other buffer (its last readers finished
        // before the sync that ended iteration it-1)
        if (it + 1 < NIT) {
            const int nxt = cur ^ 1;
#pragma unroll
            for (int i = 0; i < 2; i++) {
                int kr = krA + 8 * i;
                *(float4*)&As[nxt][kr][chA] = pa[i];
                *(float4*)&Bs[nxt][kr][chA] = pb[i];
            }
        }
        __syncthreads();
    }

    // ---- epilogue ----
    if (STAGE == 1) {
        float* Hbase = g_h + (size_t)tile * DIM * 128;
#pragma unroll
        for (int mi = 0; mi < 4; mi++) {
            int mA = wm + mi * 16 + g;
            int mB = mA + 8;
#pragma unroll
            for (int nj = 0; nj < 4; nj++) {
                int n = n0 + wn + nj * 8 + t4 * 2;
                float bi0 = Bias[e * DIM + n];
                float bi1 = Bias[e * DIM + n + 1];
                float v0 = acc[mi][nj][0] + bi0;
                float v1 = acc[mi][nj][1] + bi1;
                float v2 = acc[mi][nj][2] + bi0;
                float v3 = acc[mi][nj][3] + bi1;
                Hbase[(size_t)n * 128 + mA]       = to_tf32(0.5f * v0 * (1.0f + erff(v0 * 0.70710678118654752f)));
                Hbase[(size_t)(n + 1) * 128 + mA] = to_tf32(0.5f * v1 * (1.0f + erff(v1 * 0.70710678118654752f)));
                Hbase[(size_t)n * 128 + mB]       = to_tf32(0.5f * v2 * (1.0f + erff(v2 * 0.70710678118654752f)));
                Hbase[(size_t)(n + 1) * 128 + mB] = to_tf32(0.5f * v3 * (1.0f + erff(v3 * 0.70710678118654752f)));
            }
        }
    } else {
        const int prow = off + m0;
#pragma unroll
        for (int mi = 0; mi < 4; mi++) {
            int mA = wm + mi * 16 + g;
            int mB = mA + 8;
            int tokA = g_pperm[prow + mA];
            int tokB = g_pperm[prow + mB];
            float wA = (tokA >= 0) ? g_w[tokA] : 0.f;
            float wB = (tokB >= 0) ? g_w[tokB] : 0.f;
#pragma unroll
            for (int nj = 0; nj < 4; nj++) {
                int n = n0 + wn + nj * 8 + t4 * 2;
                float bi0 = Bias[e * DIM + n];
                float bi1 = Bias[e * DIM + n + 1];
                if (tokA >= 0) {
                    out[(size_t)tokA * DIM + n]     = wA * (acc[mi][nj][0] + bi0);
                    out[(size_t)tokA * DIM + n + 1] = wA * (acc[mi][nj][1] + bi1);
                }
                if (tokB >= 0) {
                    out[(size_t)tokB * DIM + n]     = wB * (acc[mi][nj][2] + bi0);
                    out[(size_t)tokB * DIM + n + 1] = wB * (acc[mi][nj][3] + bi1);
                }
            }
        }
    }
}

// ---------------------------------------------------------------------------
extern "C" void kernel_launch(void* const* d_in, const int* in_sizes, int n_in,
                              void* d_out, int out_size) {
    const float* x  = (const float*)d_in[0];
    const float* Wg = (const float*)d_in[1];
    const float* bg = (const float*)d_in[2];
    const float* W1 = (const float*)d_in[3];
    const float* b1 = (const float*)d_in[4];
    const float* W2 = (const float*)d_in[5];
    const float* b2 = (const float*)d_in[6];
    float* out = (float*)d_out;

    prep_kernel<<<16384, 256>>>(W1, W2);                       // 1
    gate_kernel<<<(NTOK * 32 + 255) / 256, 256>>>(x, Wg, bg);  // 2
    scan_kernel<<<1, 32>>>();                                  // 3
    scatter_kernel<<<(NTOK + 255) / 256, 256>>>();             // 4
    copyxp_kernel<<<PADTILES, 256>>>(x);                       // 5

    dim3 grid(DIM / BN, PADTILES, NEXP);
    gemm_mma<1><<<grid, 256>>>(b1, nullptr);                   // 6
    gemm_mma<2><<<grid, 256>>>(b2, out);                       // 7
}

// round 13
// speedup vs baseline: 9.3599x; 1.0640x over previous
#include <cuda_runtime.h>
#include <math.h>
#include <stdint.h>

#define NTOK 8192
#define DIM  1024
#define NEXP 8
#define BM   128
#define BN   128
#define BK   16
#define PADROWS (NTOK + NEXP*128)     // 9216 worst-case padded rows
#define PADTILES (PADROWS / 128)      // 72

// ---------------- device scratch (alloc-free rule) ----------------
// Reference ONLY from device code (host-side use gets the ATS host-shadow
// address — root cause of the R7-R10 anomalies).
__device__ int   g_eid[NTOK];
__device__ float g_w[NTOK];
__device__ int   g_counts[NEXP];
__device__ int   g_offs[NEXP];
__device__ int   g_padcnt[NEXP];
__device__ int   g_pperm[PADROWS];
// k-major blocked hidden activations: [tile][k][128 rows]
__device__ __align__(256) float g_h  [(size_t)PADTILES * DIM * 128];
// RNA-rounded weights (device-resident)
__device__ __align__(256) float g_w1r[(size_t)NEXP * DIM * DIM];
__device__ __align__(256) float g_w2r[(size_t)NEXP * DIM * DIM];

__device__ __forceinline__ float to_tf32(float v) {
    float r; asm("cvt.rna.tf32.f32 %0, %1;" : "=f"(r) : "f"(v)); return r;
}

// ---------------- fused prep: init counts + fill perm + round both W ----------------
__global__ void prep_kernel(const float* __restrict__ W1, const float* __restrict__ W2) {
    const int b = blockIdx.x, t = threadIdx.x;
    if (b == 0 && t < NEXP) g_counts[t] = 0;
    int pidx = b * 256 + t;
    if (pidx < PADROWS) g_pperm[pidx] = -1;

    size_t i = (size_t)b * 256 + t;                      // 0 .. 4M-1
    const size_t HALF = (size_t)NEXP * DIM * DIM / 4;    // 2M float4 per matrix
    if (i < HALF) {
        float4 v = ((const float4*)W1)[i];
        v.x = to_tf32(v.x); v.y = to_tf32(v.y); v.z = to_tf32(v.z); v.w = to_tf32(v.w);
        ((float4*)g_w1r)[i] = v;
    } else {
        size_t j = i - HALF;
        float4 v = ((const float4*)W2)[j];
        v.x = to_tf32(v.x); v.y = to_tf32(v.y); v.z = to_tf32(v.z); v.w = to_tf32(v.w);
        ((float4*)g_w2r)[j] = v;
    }
}

// ---------------- gating ----------------
__global__ void gate_kernel(const float* __restrict__ x,
                            const float* __restrict__ Wg,
                            const float* __restrict__ bg) {
    int warp = (blockIdx.x * blockDim.x + threadIdx.x) >> 5;
    int lane = threadIdx.x & 31;
    if (warp >= NTOK) return;
    const float* xr = x + (size_t)warp * DIM;
    float acc[NEXP];
#pragma unroll
    for (int e = 0; e < NEXP; e++) acc[e] = 0.f;
    for (int d = lane; d < DIM; d += 32) {
        float xv = xr[d];
        const float* wr = Wg + d * NEXP;
#pragma unroll
        for (int e = 0; e < NEXP; e++) acc[e] = fmaf(xv, wr[e], acc[e]);
    }
#pragma unroll
    for (int e = 0; e < NEXP; e++) {
#pragma unroll
        for (int o = 16; o > 0; o >>= 1)
            acc[e] += __shfl_xor_sync(0xffffffffu, acc[e], o);
    }
    if (lane == 0) {
        float l[NEXP];
        float best = -1e30f; int bi = 0;
#pragma unroll
        for (int e = 0; e < NEXP; e++) {
            l[e] = acc[e] + bg[e];
            if (l[e] > best) { best = l[e]; bi = e; }   // first-max, matches jnp.argmax
        }
        float s = 0.f;
#pragma unroll
        for (int e = 0; e < NEXP; e++) s += expf(l[e] - best);
        g_eid[warp] = bi;
        g_w[warp]   = 1.0f / s;
        atomicAdd(&g_counts[bi], 1);
    }
}

// ---------------- fused scan + scatter (single block; order within expert is free) ----
__global__ void group_kernel() {
    __shared__ int sfill[NEXP];
    const int t = threadIdx.x;   // 1024 threads
    if (t == 0) {
        int o = 0;
        for (int e = 0; e < NEXP; e++) {
            int pc = ((g_counts[e] + BM - 1) / BM) * BM;
            g_padcnt[e] = pc;
            g_offs[e]   = o;
            sfill[e]    = o;
            o += pc;
        }
    }
    __syncthreads();
    for (int tok = t; tok < NTOK; tok += 1024) {
        int e = g_eid[tok];
        int pos = atomicAdd(&sfill[e], 1);
        g_pperm[pos] = tok;
    }
}

// ---------------- tf32 mma.sync grouped GEMM ----------------
// STAGE 1: A gathered from x via g_pperm (transpose+tf32 during staging), B=g_w1r
//          -> g_h = tf32(gelu(A@W1+b1)) in k-major blocked layout
// STAGE 2: A = g_h (k-major blocked), B=g_w2r -> out[tok] = w_tok*(A@W2+b2)
// BK=16 register-prefetch double buffer at occupancy 2 (34816 B static smem).
#define MMA_TF32(d, a, b)                                                        \
    asm volatile(                                                                \
        "mma.sync.aligned.m16n8k8.row.col.f32.tf32.tf32.f32 "                    \
        "{%0,%1,%2,%3}, {%4,%5,%6,%7}, {%8,%9}, {%0,%1,%2,%3};"                  \
        : "+f"((d)[0]), "+f"((d)[1]), "+f"((d)[2]), "+f"((d)[3])                 \
        : "r"((a)[0]), "r"((a)[1]), "r"((a)[2]), "r"((a)[3]),                    \
          "r"((b)[0]), "r"((b)[1]))

template <int STAGE>
__global__ void __launch_bounds__(256, 2)
gemm_mma(const float* __restrict__ X, const float* __restrict__ Bias,
         float* __restrict__ out) {
    __shared__ float As[2][BK][136];
    __shared__ float Bs[2][BK][136];

    const int e  = blockIdx.z;
    const int m0 = blockIdx.y * BM;
    if (m0 >= g_padcnt[e]) return;
    const int n0   = blockIdx.x * BN;
    const int off  = g_offs[e];
    const int tile = (off + m0) >> 7;

    const float* Abase = g_h + (size_t)tile * DIM * 128;                      // STAGE 2
    const float* Bbase = (STAGE == 1 ? g_w1r : g_w2r) + (size_t)e * DIM * DIM;

    const int tid  = threadIdx.x;
    const int lane = tid & 31;
    const int wid  = tid >> 5;
    const int wm   = (wid >> 2) * 64;
    const int wn   = (wid & 3) * 32;
    const int g    = lane >> 2;
    const int t4   = lane & 3;

    // B staging (both stages) + stage-2 A staging: kr = tid>>5 (+8), ch = (tid&31)*4
    const int krA = tid >> 5;
    const int chA = (tid & 31) * 4;

    // stage-1 A gather coords: each thread owns row (tid>>1), 8 consecutive k
    const int arow = tid >> 1;            // 0..127
    const int ac2  = (tid & 1) * 8;       // k sub-offset 0 or 8
    const float* xrow = nullptr;
    if (STAGE == 1) {
        int tokA = g_pperm[off + m0 + arow];
        if (tokA >= 0) xrow = X + (size_t)tokA * DIM;
    }

    float4 qa0, qa1, pb0, pb1;            // prefetch registers

    float acc[4][4][4];
#pragma unroll
    for (int mi = 0; mi < 4; mi++)
#pragma unroll
        for (int nj = 0; nj < 4; nj++)
#pragma unroll
            for (int r = 0; r < 4; r++) acc[mi][nj][r] = 0.f;

    const int NIT = DIM / BK;   // 64

    // ---- staging helpers (compile-time pruned by STAGE) ----
    auto loadSlab = [&](int k0) {
        if (STAGE == 1) {
            if (xrow) {
                qa0 = *(const float4*)(xrow + k0 + ac2);
                qa1 = *(const float4*)(xrow + k0 + ac2 + 4);
            } else {
                qa0 = make_float4(0.f, 0.f, 0.f, 0.f);
                qa1 = qa0;
            }
        } else {
            qa0 = *(const float4*)(Abase + (size_t)(k0 + krA) * 128 + chA);
            qa1 = *(const float4*)(Abase + (size_t)(k0 + krA + 8) * 128 + chA);
        }
        pb0 = *(const float4*)(Bbase + (size_t)(k0 + krA) * DIM + n0 + chA);
        pb1 = *(const float4*)(Bbase + (size_t)(k0 + krA + 8) * DIM + n0 + chA);
    };
    auto storeSlab = [&](int buf) {
        if (STAGE == 1) {
            // transpose + tf32-round: As[k][m]
            As[buf][ac2 + 0][arow] = to_tf32(qa0.x);
            As[buf][ac2 + 1][arow] = to_tf32(qa0.y);
            As[buf][ac2 + 2][arow] = to_tf32(qa0.z);
            As[buf][ac2 + 3][arow] = to_tf32(qa0.w);
            As[buf][ac2 + 4][arow] = to_tf32(qa1.x);
            As[buf][ac2 + 5][arow] = to_tf32(qa1.y);
            As[buf][ac2 + 6][arow] = to_tf32(qa1.z);
            As[buf][ac2 + 7][arow] = to_tf32(qa1.w);
        } else {
            *(float4*)&As[buf][krA    ][chA] = qa0;
            *(float4*)&As[buf][krA + 8][chA] = qa1;
        }
        *(float4*)&Bs[buf][krA    ][chA] = pb0;
        *(float4*)&Bs[buf][krA + 8][chA] = pb1;
    };

    // prologue: k-slab 0 -> buf 0
    loadSlab(0);
    storeSlab(0);
    __syncthreads();

    for (int it = 0; it < NIT; ++it) {
        const int cur = it & 1;

        // prefetch next k-slab into registers (hidden under the MMAs below)
        if (it + 1 < NIT) loadSlab((it + 1) * BK);

        // compute current buffer (2 x K=8)
#pragma unroll
        for (int kk = 0; kk < 2; kk++) {
            const int kb = kk * 8;
            uint32_t a[4][4], b[4][2];
#pragma unroll
            for (int mi = 0; mi < 4; mi++) {
                int m = wm + mi * 16;
                a[mi][0] = __float_as_uint(As[cur][kb + t4    ][m + g    ]);
                a[mi][1] = __float_as_uint(As[cur][kb + t4    ][m + g + 8]);
                a[mi][2] = __float_as_uint(As[cur][kb + t4 + 4][m + g    ]);
                a[mi][3] = __float_as_uint(As[cur][kb + t4 + 4][m + g + 8]);
            }
#pragma unroll
            for (int nj = 0; nj < 4; nj++) {
                int n = wn + nj * 8;
                b[nj][0] = __float_as_uint(Bs[cur][kb + t4    ][n + g]);
                b[nj][1] = __float_as_uint(Bs[cur][kb + t4 + 4][n + g]);
            }
#pragma unroll
            for (int mi = 0; mi < 4; mi++)
#pragma unroll
                for (int nj = 0; nj < 4; nj++)
                    MMA_TF32(acc[mi][nj], a[mi], b[nj]);
        }

        // store prefetched slab into the other buffer (its last readers finished
        // before the sync that ended iteration it-1)
        if (it + 1 < NIT) storeSlab(cur ^ 1);
        __syncthreads();
    }

    // ---- epilogue ----
    if (STAGE == 1) {
        float* Hbase = g_h + (size_t)tile * DIM * 128;
#pragma unroll
        for (int mi = 0; mi < 4; mi++) {
            int mA = wm + mi * 16 + g;
            int mB = mA + 8;
#pragma unroll
            for (int nj = 0; nj < 4; nj++) {
                int n = n0 + wn + nj * 8 + t4 * 2;
                float bi0 = Bias[e * DIM + n];
                float bi1 = Bias[e * DIM + n + 1];
                float v0 = acc[mi][nj][0] + bi0;
                float v1 = acc[mi][nj][1] + bi1;
                float v2 = acc[mi][nj][2] + bi0;
                float v3 = acc[mi][nj][3] + bi1;
                Hbase[(size_t)n * 128 + mA]       = to_tf32(0.5f * v0 * (1.0f + erff(v0 * 0.70710678118654752f)));
                Hbase[(size_t)(n + 1) * 128 + mA] = to_tf32(0.5f * v1 * (1.0f + erff(v1 * 0.70710678118654752f)));
                Hbase[(size_t)n * 128 + mB]       = to_tf32(0.5f * v2 * (1.0f + erff(v2 * 0.70710678118654752f)));
                Hbase[(size_t)(n + 1) * 128 + mB] = to_tf32(0.5f * v3 * (1.0f + erff(v3 * 0.70710678118654752f)));
            }
        }
    } else {
        const int prow = off + m0;
#pragma unroll
        for (int mi = 0; mi < 4; mi++) {
            int mA = wm + mi * 16 + g;
            int mB = mA + 8;
            int tokA = g_pperm[prow + mA];
            int tokB = g_pperm[prow + mB];
            float wA = (tokA >= 0) ? g_w[tokA] : 0.f;
            float wB = (tokB >= 0) ? g_w[tokB] : 0.f;
#pragma unroll
            for (int nj = 0; nj < 4; nj++) {
                int n = n0 + wn + nj * 8 + t4 * 2;
                float bi0 = Bias[e * DIM + n];
                float bi1 = Bias[e * DIM + n + 1];
                if (tokA >= 0) {
                    out[(size_t)tokA * DIM + n]     = wA * (acc[mi][nj][0] + bi0);
                    out[(size_t)tokA * DIM + n + 1] = wA * (acc[mi][nj][1] + bi1);
                }
                if (tokB >= 0) {
                    out[(size_t)tokB * DIM + n]     = wB * (acc[mi][nj][2] + bi0);
                    out[(size_t)tokB * DIM + n + 1] = wB * (acc[mi][nj][3] + bi1);
                }
            }
        }
    }
}

// ---------------------------------------------------------------------------
extern "C" void kernel_launch(void* const* d_in, const int* in_sizes, int n_in,
                              void* d_out, int out_size) {
    const float* x  = (const float*)d_in[0];
    const float* Wg = (const float*)d_in[1];
    const float* bg = (const float*)d_in[2];
    const float* W1 = (const float*)d_in[3];
    const float* b1 = (const float*)d_in[4];
    const float* W2 = (const float*)d_in[5];
    const float* b2 = (const float*)d_in[6];
    float* out = (float*)d_out;

    prep_kernel<<<16384, 256>>>(W1, W2);                       // 1
    gate_kernel<<<(NTOK * 32 + 255) / 256, 256>>>(x, Wg, bg);  // 2
    group_kernel<<<1, 1024>>>();                               // 3

    dim3 grid(DIM / BN, PADTILES, NEXP);
    gemm_mma<1><<<grid, 256>>>(x, b1, nullptr);                // 4 <- profiled
    gemm_mma<2><<<grid, 256>>>(nullptr, b2, out);              // 5
}